// round 13
// baseline (speedup 1.0000x reference)
#include <cuda_runtime.h>
#include <cuda_fp16.h>
#include <math.h>
#include <stdint.h>

#define S_LEN 8192
#define DM    512
#define DK    16
#define DFF   2048

// ---------------- scratch (static device globals) -------------------------
__device__ __align__(256) float g_Wqkv[DM * 48];
__device__ __align__(256) float g_Woeff[DK * DM];
__device__ __align__(256) float g_mho[S_LEN * DM];    // fp32 (residual)
__device__ __align__(256) __half g_mhoh[S_LEN * DM];  // mho hi (fp16)
__device__ __align__(256) __half g_hh[S_LEN * DFF];   // gelu(h) fp16
__device__ __align__(256) __half g_w1h[DFF * DM];
__device__ __align__(256) __half g_w2h[DM * DFF];
// attention fp16 operands
__device__ __align__(256) __half g_Qh[S_LEN * DK];    // scaled by 0.25*log2e
__device__ __align__(256) __half g_Ql[S_LEN * DK];
__device__ __align__(256) __half g_Kh[S_LEN * DK];
__device__ __align__(256) __half g_Kl[S_LEN * DK];
__device__ __align__(256) __half g_Vph[S_LEN * 24];   // V padded: col16=1, 17-23=0
// split-KV partials (x4)
__device__ __align__(256) float g_po[4][S_LEN][16];   // unnormalized O
__device__ __align__(256) float g_pml[4][S_LEN][2];   // {m (log2), l}
// work queues + completion counters (reset by qkv_kernel each call)
__device__ int g_gq;
__device__ int g_aq;
__device__ int g_cnt[64];    // gemm1 tiles done per m-block (gates gemm2)

#define QSCALE 0.36067376022224085f   // 0.25 * log2(e)

// ---------------- helpers ---------------------------------------------------
__device__ __forceinline__ uint32_t smem_u32(const void* p) {
    uint32_t a;
    asm("{ .reg .u64 t; cvta.to.shared.u64 t, %1; cvt.u32.u64 %0, t; }" : "=r"(a) : "l"(p));
    return a;
}
__device__ __forceinline__ void cp16(uint32_t dst, const void* src) {
    asm volatile("cp.async.cg.shared.global [%0], [%1], 16;" :: "r"(dst), "l"(src) : "memory");
}
__device__ __forceinline__ void cp_commit() {
    asm volatile("cp.async.commit_group;" ::: "memory");
}
template <int P>
__device__ __forceinline__ void cp_wait() {
    asm volatile("cp.async.wait_group %0;" :: "n"(P) : "memory");
}
__device__ __forceinline__ void ldsm4(uint32_t addr, uint32_t& r0, uint32_t& r1,
                                      uint32_t& r2, uint32_t& r3) {
    asm volatile("ldmatrix.sync.aligned.m8n8.x4.shared.b16 {%0,%1,%2,%3}, [%4];"
                 : "=r"(r0), "=r"(r1), "=r"(r2), "=r"(r3) : "r"(addr));
}
__device__ __forceinline__ void ldsm4t(uint32_t addr, uint32_t& r0, uint32_t& r1,
                                       uint32_t& r2, uint32_t& r3) {
    asm volatile("ldmatrix.sync.aligned.m8n8.x4.trans.shared.b16 {%0,%1,%2,%3}, [%4];"
                 : "=r"(r0), "=r"(r1), "=r"(r2), "=r"(r3) : "r"(addr));
}
__device__ __forceinline__ void ldsm2t(uint32_t addr, uint32_t& r0, uint32_t& r1) {
    asm volatile("ldmatrix.sync.aligned.m8n8.x2.trans.shared.b16 {%0,%1}, [%2];"
                 : "=r"(r0), "=r"(r1) : "r"(addr));
}
__device__ __forceinline__ void mma16816(float* c, const uint32_t* a,
                                         uint32_t b0, uint32_t b1) {
    asm volatile(
        "mma.sync.aligned.m16n8k16.row.col.f32.f16.f16.f32 "
        "{%0,%1,%2,%3}, {%4,%5,%6,%7}, {%8,%9}, {%0,%1,%2,%3};"
        : "+f"(c[0]), "+f"(c[1]), "+f"(c[2]), "+f"(c[3])
        : "r"(a[0]), "r"(a[1]), "r"(a[2]), "r"(a[3]), "r"(b0), "r"(b1));
}
__device__ __forceinline__ void mma16816_z(float* c, const uint32_t* a,
                                           uint32_t b0, uint32_t b1) {
    float z = 0.f;
    asm volatile(
        "mma.sync.aligned.m16n8k16.row.col.f32.f16.f16.f32 "
        "{%0,%1,%2,%3}, {%4,%5,%6,%7}, {%8,%9}, {%10,%10,%10,%10};"
        : "=f"(c[0]), "=f"(c[1]), "=f"(c[2]), "=f"(c[3])
        : "r"(a[0]), "r"(a[1]), "r"(a[2]), "r"(a[3]), "r"(b0), "r"(b1), "f"(z));
}
__device__ __forceinline__ float ex2f(float x) {
    float y;
    asm("ex2.approx.ftz.f32 %0, %1;" : "=f"(y) : "f"(x));
    return y;
}
__device__ __forceinline__ uint32_t f16x2_pack(float hi, float lo) {
    uint32_t d;
    asm("cvt.rn.f16x2.f32 %0, %1, %2;" : "=r"(d) : "f"(hi), "f"(lo));
    return d;
}
__device__ __forceinline__ void h_split(float x, __half& hi, __half& lo) {
    hi = __float2half_rn(x);
    lo = __float2half_rn(x - __half2float(hi));
}

// ---------------- prep: pack Wqkv + Woeff + fp16 weights (ONE launch) ------
__global__ void prep_kernel(const float* __restrict__ Wq,
                            const float* __restrict__ Wk,
                            const float* __restrict__ Wv,
                            const float* __restrict__ Wo,
                            const float* __restrict__ w1,
                            const float* __restrict__ w2) {
    int idx = blockIdx.x * blockDim.x + threadIdx.x;
    if (idx < DM * 48) {
        int d = idx / 48, c = idx % 48;
        float v;
        if (c < 16)      v = Wq[d * 16 + c];
        else if (c < 32) v = Wk[d * 16 + c - 16];
        else             v = Wv[d * 16 + c - 32];
        g_Wqkv[idx] = v;
    }
    if (idx < DK * DM) {
        int i = idx / DM, c = idx % DM;
        float s = 0.f;
#pragma unroll
        for (int h = 0; h < 8; h++) s += Wo[(h * 16 + i) * DM + c];
        g_Woeff[idx] = s;
    }
    if (idx < DFF * DM) {
        g_w1h[idx] = __float2half_rn(w1[idx]);
        g_w2h[idx] = __float2half_rn(w2[idx]);
    }
}

// ---------------- fused QKV projection: 64 rows/CTA, 128 CTAs --------------
__global__ void __launch_bounds__(256) qkv_kernel(const float* __restrict__ frame) {
    __shared__ float Fs[64][33];
    __shared__ float Ws[32][48];
    int t = threadIdx.x;
    int m0 = blockIdx.x * 64;
    int r = t & 63;
    int seg = t >> 6;        // 0..3 -> 12 cols each

    if (blockIdx.x == 0) {   // reset work queues + counters for this call
        if (t == 0) { g_gq = 0; g_aq = 0; }
        if (t < 64) g_cnt[t] = 0;
    }

    float acc[12];
#pragma unroll
    for (int c = 0; c < 12; c++) acc[c] = 0.f;

    int lrow = t >> 2;          // 0..63
    int lds  = (t & 3) * 8;     // 0,8,16,24

    for (int d0 = 0; d0 < DM; d0 += 32) {
        {
            float4 v0 = *(const float4*)&frame[(size_t)(m0 + lrow) * DM + d0 + lds];
            float4 v1 = *(const float4*)&frame[(size_t)(m0 + lrow) * DM + d0 + lds + 4];
            Fs[lrow][lds + 0] = v0.x; Fs[lrow][lds + 1] = v0.y;
            Fs[lrow][lds + 2] = v0.z; Fs[lrow][lds + 3] = v0.w;
            Fs[lrow][lds + 4] = v1.x; Fs[lrow][lds + 5] = v1.y;
            Fs[lrow][lds + 6] = v1.z; Fs[lrow][lds + 7] = v1.w;
        }
        for (int q = t; q < 32 * 48; q += 256)
            Ws[q / 48][q % 48] = g_Wqkv[(d0 + q / 48) * 48 + (q % 48)];
        __syncthreads();
#pragma unroll
        for (int d = 0; d < 32; d++) {
            float f = Fs[r][d];
#pragma unroll
            for (int c = 0; c < 12; c++)
                acc[c] = fmaf(f, Ws[d][seg * 12 + c], acc[c]);
        }
        __syncthreads();
    }
    int row = m0 + r;
#pragma unroll
    for (int c = 0; c < 12; c++) {
        int cg = seg * 12 + c;
        __half h, l;
        if (cg < 16) {
            h_split(acc[c] * QSCALE, h, l);
            g_Qh[row * 16 + cg] = h;
            g_Ql[row * 16 + cg] = l;
        } else if (cg < 32) {
            h_split(acc[c], h, l);
            g_Kh[row * 16 + cg - 16] = h;
            g_Kl[row * 16 + cg - 16] = l;
        } else {
            g_Vph[row * 24 + cg - 32] = __float2half_rn(acc[c]);
        }
    }
    if (seg == 0) {
#pragma unroll
        for (int c2 = 16; c2 < 24; c2++)
            g_Vph[row * 24 + c2] = (c2 == 16) ? __float2half_rn(1.0f) : __float2half_rn(0.0f);
    }
}

// ---------------- persistent tensor-core flash attention --------------------
// 512 items = 128 q-tiles x 4 KV splits, dynamic queue over 444 CTAs.
// S = QH*KH + QH*KL + QL*KH; PV: single V (linear averaging), ones-column l.
static constexpr uint32_t ATT_STG  = 18432;   // Kh(6144)+Kl(6144)+Vh(6144)
static constexpr uint32_t ATT_QH   = 55296;   // after 3 stages
static constexpr uint32_t ATT_QL   = 58368;
static constexpr uint32_t ATT_SMEM = 61440;

__device__ __forceinline__ void attn_load(uint32_t stg, int k0, int t) {
#pragma unroll
    for (int i = 0; i < 2; i++) {
        int q = t + i * 128;
        int row = q >> 1, g = q & 1;
        cp16(stg + (uint32_t)row * 48 + g * 16, g_Kh + (size_t)(k0 + row) * 16 + g * 8);
        cp16(stg + 6144 + (uint32_t)row * 48 + g * 16, g_Kl + (size_t)(k0 + row) * 16 + g * 8);
    }
#pragma unroll
    for (int i = 0; i < 3; i++) {
        int q = t + i * 128;
        int row = q / 3, g = q % 3;
        cp16(stg + 12288 + (uint32_t)row * 48 + g * 16, g_Vph + (size_t)(k0 + row) * 24 + g * 8);
    }
}

__global__ void __launch_bounds__(128, 3) attn_tc() {
    extern __shared__ __align__(128) char sm[];
    __shared__ int sm_it;
    uint32_t sb = smem_u32(sm);
    int t = threadIdx.x, lane = t & 31, w = t >> 5;

    uint32_t aQ  = sb + ATT_QH + (uint32_t)(w * 16 + (lane & 15)) * 48 + (uint32_t)(lane >> 4) * 16;
    uint32_t aK  = (uint32_t)((lane & 7) + ((lane >> 4) & 1) * 8) * 48 + (uint32_t)((lane >> 3) & 1) * 16;
    uint32_t aV4 = (uint32_t)((lane & 7) + ((lane >> 3) & 1) * 8) * 48 + (uint32_t)(lane >> 4) * 16;
    uint32_t aV2 = (uint32_t)((lane & 7) + ((lane >> 3) & 1) * 8) * 48 + 32;

    for (;;) {
        __syncthreads();
        if (t == 0) sm_it = atomicAdd(&g_aq, 1);
        __syncthreads();
        int it = sm_it;
        if (it >= 512) return;
        int q0 = (it >> 2) * 64;
        int ks = it & 3;
        int kbase = ks * 2048;

        {
            int row = t >> 1, g = t & 1;
            cp16(sb + ATT_QH + (uint32_t)row * 48 + g * 16, g_Qh + (size_t)(q0 + row) * 16 + g * 8);
            cp16(sb + ATT_QL + (uint32_t)row * 48 + g * 16, g_Ql + (size_t)(q0 + row) * 16 + g * 8);
        }
        attn_load(sb, kbase, t);
        cp_commit();
        attn_load(sb + ATT_STG, kbase + 128, t);
        cp_commit();

        uint32_t QH[4], QL[4];
        float o[3][4];
#pragma unroll
        for (int i = 0; i < 3; i++)
#pragma unroll
            for (int j = 0; j < 4; j++) o[i][j] = 0.f;
        float m0 = -INFINITY, m8 = -INFINITY;

        int sidx = 0;
        for (int c = 0; c < 16; c++) {
            if (c == 15) cp_wait<0>(); else cp_wait<1>();
            __syncthreads();
            if (c == 0) {
                ldsm4(aQ, QH[0], QH[1], QH[2], QH[3]);
                ldsm4(aQ + (ATT_QL - ATT_QH), QL[0], QL[1], QL[2], QL[3]);
            }
            if (c + 2 < 16) {
                int pidx = sidx + 2; if (pidx >= 3) pidx -= 3;
                attn_load(sb + (uint32_t)pidx * ATT_STG, kbase + (c + 2) * 128, t);
                cp_commit();
            }
            uint32_t stg = sb + (uint32_t)sidx * ATT_STG;

            float s[16][4];
#pragma unroll
            for (int u = 0; u < 8; u++) {
                uint32_t bh0, bh1, bh2, bh3, bl0, bl1, bl2, bl3;
                ldsm4(stg + u * 768 + aK, bh0, bh1, bh2, bh3);
                ldsm4(stg + 6144 + u * 768 + aK, bl0, bl1, bl2, bl3);
                mma16816_z(s[2 * u], QH, bh0, bh1);
                mma16816(s[2 * u], QH, bl0, bl1);
                mma16816(s[2 * u], QL, bh0, bh1);
                mma16816_z(s[2 * u + 1], QH, bh2, bh3);
                mma16816(s[2 * u + 1], QH, bl2, bl3);
                mma16816(s[2 * u + 1], QL, bh2, bh3);
            }

            float mx0 = s[0][0], mx8 = s[0][2];
#pragma unroll
            for (int nt = 0; nt < 16; nt++) {
                mx0 = fmaxf(mx0, fmaxf(s[nt][0], s[nt][1]));
                mx8 = fmaxf(mx8, fmaxf(s[nt][2], s[nt][3]));
            }
            mx0 = fmaxf(mx0, __shfl_xor_sync(0xffffffffu, mx0, 1));
            mx0 = fmaxf(mx0, __shfl_xor_sync(0xffffffffu, mx0, 2));
            mx8 = fmaxf(mx8, __shfl_xor_sync(0xffffffffu, mx8, 1));
            mx8 = fmaxf(mx8, __shfl_xor_sync(0xffffffffu, mx8, 2));
            float mn0 = fmaxf(m0, mx0), mn8 = fmaxf(m8, mx8);
            float c0 = ex2f(m0 - mn0), c8 = ex2f(m8 - mn8);
            m0 = mn0; m8 = mn8;
#pragma unroll
            for (int i = 0; i < 3; i++) {
                o[i][0] *= c0; o[i][1] *= c0; o[i][2] *= c8; o[i][3] *= c8;
            }
#pragma unroll
            for (int nt = 0; nt < 16; nt++) {
                s[nt][0] = ex2f(s[nt][0] - m0);
                s[nt][1] = ex2f(s[nt][1] - m0);
                s[nt][2] = ex2f(s[nt][2] - m8);
                s[nt][3] = ex2f(s[nt][3] - m8);
            }

#pragma unroll
            for (int j = 0; j < 8; j++) {
                uint32_t a[4];
                a[0] = f16x2_pack(s[2 * j][1],     s[2 * j][0]);
                a[1] = f16x2_pack(s[2 * j][3],     s[2 * j][2]);
                a[2] = f16x2_pack(s[2 * j + 1][1], s[2 * j + 1][0]);
                a[3] = f16x2_pack(s[2 * j + 1][3], s[2 * j + 1][2]);
                uint32_t v0, v1, v2, v3, v4, v5;
                ldsm4t(stg + 12288 + j * 768 + aV4, v0, v1, v2, v3);
                ldsm2t(stg + 12288 + j * 768 + aV2, v4, v5);
                mma16816(o[0], a, v0, v1);
                mma16816(o[1], a, v2, v3);
                mma16816(o[2], a, v4, v5);
            }
            if (++sidx == 3) sidx = 0;
        }

        float l0 = __shfl_sync(0xffffffffu, o[2][0], lane & 28);
        float l8 = __shfl_sync(0xffffffffu, o[2][2], lane & 28);
        int row0 = q0 + w * 16 + (lane >> 2);
        int c4 = (lane & 3) * 2;
        *(float2*)&g_po[ks][row0][c4]         = make_float2(o[0][0], o[0][1]);
        *(float2*)&g_po[ks][row0][8 + c4]     = make_float2(o[1][0], o[1][1]);
        *(float2*)&g_po[ks][row0 + 8][c4]     = make_float2(o[0][2], o[0][3]);
        *(float2*)&g_po[ks][row0 + 8][8 + c4] = make_float2(o[1][2], o[1][3]);
        if ((lane & 3) == 0) {
            *(float2*)&g_pml[ks][row0][0]     = make_float2(m0, l0);
            *(float2*)&g_pml[ks][row0 + 8][0] = make_float2(m8, l8);
        }
    }
}

// ---------------- mho = merge(partials) @ Woeff (fp32 + fp16 hi) -----------
__global__ void __launch_bounds__(256) mho_kernel() {
    __shared__ float hrow[8][16];
    int t = threadIdx.x;
    int r0 = blockIdx.x * 8;
    if (t < 128) {
        int row = r0 + (t >> 4), col = t & 15;
        float mm = -INFINITY;
#pragma unroll
        for (int k = 0; k < 4; k++) mm = fmaxf(mm, g_pml[k][row][0]);
        float l = 0.f, acc = 0.f;
#pragma unroll
        for (int k = 0; k < 4; k++) {
            float2 s = *(const float2*)&g_pml[k][row][0];
            float a = ex2f(s.x - mm);
            l = fmaf(s.y, a, l);
            acc = fmaf(g_po[k][row][col], a, acc);
        }
        hrow[t >> 4][col] = acc * __fdividef(1.f, l);
    }
    __syncthreads();

    int cg = (t & 127) * 4;
    int rb = (t >> 7) * 4;
    float4 a[4];
#pragma unroll
    for (int r = 0; r < 4; r++) a[r] = make_float4(0.f, 0.f, 0.f, 0.f);
#pragma unroll
    for (int i = 0; i < 16; i++) {
        float4 w = *(const float4*)&g_Woeff[i * 512 + cg];
#pragma unroll
        for (int r = 0; r < 4; r++) {
            float h = hrow[rb + r][i];
            a[r].x = fmaf(h, w.x, a[r].x); a[r].y = fmaf(h, w.y, a[r].y);
            a[r].z = fmaf(h, w.z, a[r].z); a[r].w = fmaf(h, w.w, a[r].w);
        }
    }
#pragma unroll
    for (int r = 0; r < 4; r++) {
        size_t base = (size_t)(r0 + rb + r) * 512 + cg;
        *(float4*)&g_mho[base] = a[r];
        __half2 h01, h23;
        h01.x = __float2half_rn(a[r].x); h01.y = __float2half_rn(a[r].y);
        h23.x = __float2half_rn(a[r].z); h23.y = __float2half_rn(a[r].w);
        *(__half2*)&g_mhoh[base + 0] = h01;
        *(__half2*)&g_mhoh[base + 2] = h23;
    }
}

// ---------------- fused persistent FFN GEMM kernel -------------------------
// Items [0,1024): gemm1 tiles, gelu epilogue -> g_hh.
// Items [1024,1280): gemm2 tiles, gated on g_cnt[mblk]==16.
static constexpr int G_STAGE = 20480;   // A(10240)+B(10240)
static constexpr int G_SMEM  = 67584;   // epilogue 128x132 fp32 dominates
static constexpr int N_ITEMS = 1024 + 256;

__device__ __forceinline__ void g3_load(uint32_t stg, int m0, int n0, int k0, int t,
                                        int ldk,
                                        const __half* __restrict__ Ah,
                                        const __half* __restrict__ Bh) {
#pragma unroll
    for (int i = 0; i < 2; i++) {
        int q = t + i * 256;
        int r = q >> 2, gr = q & 3;
        uint32_t off = (uint32_t)r * 80 + gr * 16;
        size_t gidx = (size_t)r * ldk + k0 + gr * 8;
        cp16(stg + off,         Ah + (size_t)m0 * ldk + gidx);
        cp16(stg + 10240 + off, Bh + (size_t)n0 * ldk + gidx);
    }
}

__global__ void __launch_bounds__(256, 2) gemm_fused(
    const float* __restrict__ fc1_b, const float* __restrict__ fc2_b,
    float* __restrict__ outf)
{
    extern __shared__ __align__(128) char sm[];
    __shared__ int sm_item;
    uint32_t sbase = smem_u32(sm);

    int t = threadIdx.x;
    int wid = t >> 5, lane = t & 31;
    int wm = wid & 3, wn = wid >> 2;

    int a_row = lane & 15;
    int a_kg  = lane >> 4;
    int b_row = ((lane >> 4) << 3) + (lane & 7);
    int b_kg  = (lane >> 3) & 1;

    for (;;) {
        __syncthreads();
        if (t == 0) sm_item = atomicAdd(&g_gq, 1);
        __syncthreads();
        int item = sm_item;
        if (item >= N_ITEMS) return;

        const __half* Ap;
        const __half* Bp;
        const float* bias;
        int m0, n0, ldk, NC, N, epi, mblk;
        if (item < 1024) {
            mblk = item >> 4;
            m0 = mblk << 7; n0 = (item & 15) << 7;
            Ap = g_mhoh; Bp = g_w1h; bias = fc1_b;
            ldk = DM; NC = DM / 32; N = DFF; epi = 0;
        } else {
            int idx = item - 1024;
            mblk = idx >> 2;
            m0 = mblk << 7; n0 = (idx & 3) << 7;
            Ap = g_hh; Bp = g_w2h; bias = fc2_b;
            ldk = DFF; NC = DFF / 32; N = DM; epi = 1;
            if (t == 0) {                       // wait for gemm1 rows
                while (atomicAdd(&g_cnt[mblk], 0) < 16) {}
            }
            __syncthreads();
            __threadfence();
        }

        float acc[2][8][4];
#pragma unroll
        for (int i = 0; i < 2; i++)
#pragma unroll
            for (int j = 0; j < 8; j++)
#pragma unroll
                for (int k = 0; k < 4; k++) acc[i][j][k] = 0.f;

        g3_load(sbase, m0, n0, 0, t, ldk, Ap, Bp);
        cp_commit();
        g3_load(sbase + G_STAGE, m0, n0, 32, t, ldk, Ap, Bp);
        cp_commit();

        int sidx = 0;
        for (int c = 0; c < NC; c++) {
            if (c == NC - 1) cp_wait<0>(); else cp_wait<1>();
            __syncthreads();
            if (c + 2 < NC) {
                int pidx = sidx + 2; if (pidx >= 3) pidx -= 3;
                g3_load(sbase + (uint32_t)pidx * G_STAGE, m0, n0, (c + 2) * 32, t, ldk, Ap, Bp);
                cp_commit();
            }
            uint32_t stg = sbase + (uint32_t)sidx * G_STAGE;
            uint32_t sAh = stg, sBh = stg + 10240;

#pragma unroll
            for (int ks = 0; ks < 2; ks++) {
                uint32_t ah[2][4];
#pragma unroll
                for (int mt = 0; mt < 2; mt++) {
                    uint32_t off = (uint32_t)(wm * 32 + mt * 16 + a_row) * 80
                                 + (uint32_t)(ks * 32 + a_kg * 16);
                    ldsm4(sAh + off, ah[mt][0], ah[mt][1], ah[mt][2], ah[mt][3]);
                }
#pragma unroll
                for (int np = 0; np < 4; np++) {
                    uint32_t boff = (uint32_t)(wn * 64 + np * 16 + b_row) * 80
                                  + (uint32_t)(ks * 32 + b_kg * 16);
                    uint32_t bh0, bh1, bh2, bh3;
                    ldsm4(sBh + boff, bh0, bh1, bh2, bh3);
#pragma unroll
                    for (int mt = 0; mt < 2; mt++) {
                        mma16816(acc[mt][np * 2 + 0], ah[mt], bh0, bh1);
                        mma16816(acc[mt][np * 2 + 1], ah[mt], bh2, bh3);
                    }
                }
            }
            if (++sidx == 3) sidx = 0;
        }

        // epilogue: stage accums to smem, coalesced out
        __syncthreads();
        float* eb = (float*)sm;                 // 128 x 132 fp32
#pragma unroll
        for (int mt = 0; mt < 2; mt++) {
#pragma unroll
            for (int nt = 0; nt < 8; nt++) {
                int row = wm * 32 + mt * 16 + (lane >> 2);
                int col = wn * 64 + nt * 8 + (lane & 3) * 2;
                float* p0 = &eb[row * 132 + col];
                p0[0] = acc[mt][nt][0]; p0[1] = acc[mt][nt][1];
                float* p1 = &eb[(row + 8) * 132 + col];
                p1[0] = acc[mt][nt][2]; p1[1] = acc[mt][nt][3];
            }
        }
        __syncthreads();

        int cp2 = (t & 63) * 2;
        float b0 = bias[n0 + cp2], b1 = bias[n0 + cp2 + 1];
#pragma unroll 4
        for (int i = 0; i < 32; i++) {
            int row = (t >> 6) + i * 4;
            float2 v = *(float2*)&eb[row * 132 + cp2];
            float x0 = v.x + b0, x1 = v.y + b1;
            size_t oidx = (size_t)(m0 + row) * N + n0 + cp2;
            if (epi == 0) {
                x0 = 0.5f * x0 * (1.0f + erff(x0 * 0.70710678118654752f));
                x1 = 0.5f * x1 * (1.0f + erff(x1 * 0.70710678118654752f));
                __half2 hp;
                hp.x = __float2half_rn(x0); hp.y = __float2half_rn(x1);
                *(__half2*)&g_hh[oidx] = hp;
            } else {
                float2 rr = *(const float2*)&g_mho[oidx];
                *(float2*)&outf[oidx] = make_float2(x0 + rr.x, x1 + rr.y);
            }
        }

        if (epi == 0) {
            __threadfence();
            __syncthreads();
            if (t == 0) atomicAdd(&g_cnt[mblk], 1);
        }
    }
}

// ---------------- launch ---------------------------------------------------
extern "C" void kernel_launch(void* const* d_in, const int* in_sizes, int n_in,
                              void* d_out, int out_size) {
    const float* frame = (const float*)d_in[0];
    const float* W_q   = (const float*)d_in[1];
    const float* W_k   = (const float*)d_in[2];
    const float* W_v   = (const float*)d_in[3];
    const float* W_o   = (const float*)d_in[4];
    const float* fc1_w = (const float*)d_in[5];
    const float* fc1_b = (const float*)d_in[6];
    const float* fc2_w = (const float*)d_in[7];
    const float* fc2_b = (const float*)d_in[8];
    float* out = (float*)d_out;

    cudaFuncSetAttribute(gemm_fused,
                         cudaFuncAttributeMaxDynamicSharedMemorySize, G_SMEM);
    cudaFuncSetAttribute(attn_tc,
                         cudaFuncAttributeMaxDynamicSharedMemorySize, ATT_SMEM);

    prep_kernel<<<(DFF * DM + 255) / 256, 256>>>(W_q, W_k, W_v, W_o, fc1_w, fc2_w);
    qkv_kernel<<<S_LEN / 64, 256>>>(frame);
    attn_tc<<<148 * 3, 128, ATT_SMEM>>>();
    mho_kernel<<<S_LEN / 8, 256>>>();
    gemm_fused<<<148 * 2, 256, G_SMEM>>>(fc1_b, fc2_b, out);
}

// round 14
// speedup vs baseline: 1.4856x; 1.4856x over previous
#include <cuda_runtime.h>
#include <cuda_fp16.h>
#include <math.h>
#include <stdint.h>

#define S_LEN 8192
#define DM    512
#define DK    16
#define DFF   2048

// ---------------- scratch (static device globals) -------------------------
__device__ __align__(256) float g_Wqkv[DM * 48];
__device__ __align__(256) float g_Woeff[DK * DM];
__device__ __align__(256) float g_mho[S_LEN * DM];    // fp32 (residual)
__device__ __align__(256) __half g_mhoh[S_LEN * DM];  // mho hi (fp16)
__device__ __align__(256) __half g_hh[S_LEN * DFF];   // gelu(h) fp16
__device__ __align__(256) __half g_w1h[DFF * DM];
__device__ __align__(256) __half g_w2h[DM * DFF];
// attention fp16 operands
__device__ __align__(256) __half g_Qh[S_LEN * DK];    // scaled by 0.25*log2e
__device__ __align__(256) __half g_Ql[S_LEN * DK];
__device__ __align__(256) __half g_Kh[S_LEN * DK];
__device__ __align__(256) __half g_Kl[S_LEN * DK];
__device__ __align__(256) __half g_Vph[S_LEN * 24];   // V padded: col16=1, 17-23=0
// split-KV partials (x4)
__device__ __align__(256) float g_po[4][S_LEN][16];   // unnormalized O
__device__ __align__(256) float g_pml[4][S_LEN][2];   // {m (log2), l}
// work queues + completion counters (reset by qkv_kernel each call)
__device__ int g_gq;
__device__ int g_aq;
__device__ int g_cnt[64];    // gemm1 tiles done per m-block (gates gemm2)

#define QSCALE 0.36067376022224085f   // 0.25 * log2(e)

// ---------------- helpers ---------------------------------------------------
__device__ __forceinline__ uint32_t smem_u32(const void* p) {
    uint32_t a;
    asm("{ .reg .u64 t; cvta.to.shared.u64 t, %1; cvt.u32.u64 %0, t; }" : "=r"(a) : "l"(p));
    return a;
}
__device__ __forceinline__ void cp16(uint32_t dst, const void* src) {
    asm volatile("cp.async.cg.shared.global [%0], [%1], 16;" :: "r"(dst), "l"(src) : "memory");
}
__device__ __forceinline__ void cp_commit() {
    asm volatile("cp.async.commit_group;" ::: "memory");
}
template <int P>
__device__ __forceinline__ void cp_wait() {
    asm volatile("cp.async.wait_group %0;" :: "n"(P) : "memory");
}
__device__ __forceinline__ void ldsm4(uint32_t addr, uint32_t& r0, uint32_t& r1,
                                      uint32_t& r2, uint32_t& r3) {
    asm volatile("ldmatrix.sync.aligned.m8n8.x4.shared.b16 {%0,%1,%2,%3}, [%4];"
                 : "=r"(r0), "=r"(r1), "=r"(r2), "=r"(r3) : "r"(addr));
}
__device__ __forceinline__ void ldsm4t(uint32_t addr, uint32_t& r0, uint32_t& r1,
                                       uint32_t& r2, uint32_t& r3) {
    asm volatile("ldmatrix.sync.aligned.m8n8.x4.trans.shared.b16 {%0,%1,%2,%3}, [%4];"
                 : "=r"(r0), "=r"(r1), "=r"(r2), "=r"(r3) : "r"(addr));
}
__device__ __forceinline__ void ldsm2t(uint32_t addr, uint32_t& r0, uint32_t& r1) {
    asm volatile("ldmatrix.sync.aligned.m8n8.x2.trans.shared.b16 {%0,%1}, [%2];"
                 : "=r"(r0), "=r"(r1) : "r"(addr));
}
__device__ __forceinline__ void mma16816(float* c, const uint32_t* a,
                                         uint32_t b0, uint32_t b1) {
    asm volatile(
        "mma.sync.aligned.m16n8k16.row.col.f32.f16.f16.f32 "
        "{%0,%1,%2,%3}, {%4,%5,%6,%7}, {%8,%9}, {%0,%1,%2,%3};"
        : "+f"(c[0]), "+f"(c[1]), "+f"(c[2]), "+f"(c[3])
        : "r"(a[0]), "r"(a[1]), "r"(a[2]), "r"(a[3]), "r"(b0), "r"(b1));
}
__device__ __forceinline__ void mma16816_z(float* c, const uint32_t* a,
                                           uint32_t b0, uint32_t b1) {
    float z = 0.f;
    asm volatile(
        "mma.sync.aligned.m16n8k16.row.col.f32.f16.f16.f32 "
        "{%0,%1,%2,%3}, {%4,%5,%6,%7}, {%8,%9}, {%10,%10,%10,%10};"
        : "=f"(c[0]), "=f"(c[1]), "=f"(c[2]), "=f"(c[3])
        : "r"(a[0]), "r"(a[1]), "r"(a[2]), "r"(a[3]), "r"(b0), "r"(b1), "f"(z));
}
__device__ __forceinline__ float ex2f(float x) {
    float y;
    asm("ex2.approx.ftz.f32 %0, %1;" : "=f"(y) : "f"(x));
    return y;
}
__device__ __forceinline__ uint32_t f16x2_pack(float hi, float lo) {
    uint32_t d;
    asm("cvt.rn.f16x2.f32 %0, %1, %2;" : "=r"(d) : "f"(hi), "f"(lo));
    return d;
}
__device__ __forceinline__ void h_split(float x, __half& hi, __half& lo) {
    hi = __float2half_rn(x);
    lo = __float2half_rn(x - __half2float(hi));
}

// ---------------- weight packing ------------------------------------------
__global__ void pack_weights(const float* __restrict__ Wq,
                             const float* __restrict__ Wk,
                             const float* __restrict__ Wv,
                             const float* __restrict__ Wo) {
    int idx = blockIdx.x * blockDim.x + threadIdx.x;
    if (idx < DM * 48) {
        int d = idx / 48, c = idx % 48;
        float v;
        if (c < 16)      v = Wq[d * 16 + c];
        else if (c < 32) v = Wk[d * 16 + c - 16];
        else             v = Wv[d * 16 + c - 32];
        g_Wqkv[idx] = v;
    }
    if (idx < DK * DM) {
        int i = idx / DM, c = idx % DM;
        float s = 0.f;
#pragma unroll
        for (int h = 0; h < 8; h++) s += Wo[(h * 16 + i) * DM + c];
        g_Woeff[idx] = s;
    }
}

__global__ void conv_weights(const float* __restrict__ w1, const float* __restrict__ w2) {
    int i = blockIdx.x * blockDim.x + threadIdx.x;
    if (i < DFF * DM) {
        g_w1h[i] = __float2half_rn(w1[i]);
        g_w2h[i] = __float2half_rn(w2[i]);
    }
}

// ---------------- fused QKV projection: 64 rows/CTA, 128 CTAs --------------
__global__ void __launch_bounds__(256) qkv_kernel(const float* __restrict__ frame) {
    __shared__ float Fs[64][33];
    __shared__ float Ws[32][48];
    int t = threadIdx.x;
    int m0 = blockIdx.x * 64;
    int r = t & 63;
    int seg = t >> 6;        // 0..3 -> 12 cols each

    if (blockIdx.x == 0) {   // reset work queues + counters for this call
        if (t == 0) { g_gq = 0; g_aq = 0; }
        if (t < 64) g_cnt[t] = 0;
    }

    float acc[12];
#pragma unroll
    for (int c = 0; c < 12; c++) acc[c] = 0.f;

    int lrow = t >> 2;          // 0..63
    int lds  = (t & 3) * 8;     // 0,8,16,24

    for (int d0 = 0; d0 < DM; d0 += 32) {
        {
            float4 v0 = *(const float4*)&frame[(size_t)(m0 + lrow) * DM + d0 + lds];
            float4 v1 = *(const float4*)&frame[(size_t)(m0 + lrow) * DM + d0 + lds + 4];
            Fs[lrow][lds + 0] = v0.x; Fs[lrow][lds + 1] = v0.y;
            Fs[lrow][lds + 2] = v0.z; Fs[lrow][lds + 3] = v0.w;
            Fs[lrow][lds + 4] = v1.x; Fs[lrow][lds + 5] = v1.y;
            Fs[lrow][lds + 6] = v1.z; Fs[lrow][lds + 7] = v1.w;
        }
        for (int q = t; q < 32 * 48; q += 256)
            Ws[q / 48][q % 48] = g_Wqkv[(d0 + q / 48) * 48 + (q % 48)];
        __syncthreads();
#pragma unroll
        for (int d = 0; d < 32; d++) {
            float f = Fs[r][d];
#pragma unroll
            for (int c = 0; c < 12; c++)
                acc[c] = fmaf(f, Ws[d][seg * 12 + c], acc[c]);
        }
        __syncthreads();
    }
    int row = m0 + r;
#pragma unroll
    for (int c = 0; c < 12; c++) {
        int cg = seg * 12 + c;
        __half h, l;
        if (cg < 16) {
            h_split(acc[c] * QSCALE, h, l);
            g_Qh[row * 16 + cg] = h;
            g_Ql[row * 16 + cg] = l;
        } else if (cg < 32) {
            h_split(acc[c], h, l);
            g_Kh[row * 16 + cg - 16] = h;
            g_Kl[row * 16 + cg - 16] = l;
        } else {
            g_Vph[row * 24 + cg - 32] = __float2half_rn(acc[c]);
        }
    }
    if (seg == 0) {
#pragma unroll
        for (int c2 = 16; c2 < 24; c2++)
            g_Vph[row * 24 + c2] = (c2 == 16) ? __float2half_rn(1.0f) : __float2half_rn(0.0f);
    }
}

// ---------------- persistent tensor-core flash attention --------------------
// 512 items = 128 q-tiles x 4 KV splits, dynamic queue over 444 CTAs.
static constexpr uint32_t ATT_STG  = 18432;   // Kh(6144)+Kl(6144)+Vh(6144)
static constexpr uint32_t ATT_QH   = 55296;   // after 3 stages
static constexpr uint32_t ATT_QL   = 58368;
static constexpr uint32_t ATT_SMEM = 61440;

__device__ __forceinline__ void attn_load(uint32_t stg, int k0, int t) {
#pragma unroll
    for (int i = 0; i < 2; i++) {
        int q = t + i * 128;
        int row = q >> 1, g = q & 1;
        cp16(stg + (uint32_t)row * 48 + g * 16, g_Kh + (size_t)(k0 + row) * 16 + g * 8);
        cp16(stg + 6144 + (uint32_t)row * 48 + g * 16, g_Kl + (size_t)(k0 + row) * 16 + g * 8);
    }
#pragma unroll
    for (int i = 0; i < 3; i++) {
        int q = t + i * 128;
        int row = q / 3, g = q % 3;
        cp16(stg + 12288 + (uint32_t)row * 48 + g * 16, g_Vph + (size_t)(k0 + row) * 24 + g * 8);
    }
}

__global__ void __launch_bounds__(128, 3) attn_tc() {
    extern __shared__ __align__(128) char sm[];
    __shared__ int sm_it;
    uint32_t sb = smem_u32(sm);
    int t = threadIdx.x, lane = t & 31, w = t >> 5;

    uint32_t aQ  = sb + ATT_QH + (uint32_t)(w * 16 + (lane & 15)) * 48 + (uint32_t)(lane >> 4) * 16;
    uint32_t aK  = (uint32_t)((lane & 7) + ((lane >> 4) & 1) * 8) * 48 + (uint32_t)((lane >> 3) & 1) * 16;
    uint32_t aV4 = (uint32_t)((lane & 7) + ((lane >> 3) & 1) * 8) * 48 + (uint32_t)(lane >> 4) * 16;
    uint32_t aV2 = (uint32_t)((lane & 7) + ((lane >> 3) & 1) * 8) * 48 + 32;

    for (;;) {
        __syncthreads();
        if (t == 0) sm_it = atomicAdd(&g_aq, 1);
        __syncthreads();
        int it = sm_it;
        if (it >= 512) return;
        int q0 = (it >> 2) * 64;
        int ks = it & 3;
        int kbase = ks * 2048;

        {
            int row = t >> 1, g = t & 1;
            cp16(sb + ATT_QH + (uint32_t)row * 48 + g * 16, g_Qh + (size_t)(q0 + row) * 16 + g * 8);
            cp16(sb + ATT_QL + (uint32_t)row * 48 + g * 16, g_Ql + (size_t)(q0 + row) * 16 + g * 8);
        }
        attn_load(sb, kbase, t);
        cp_commit();
        attn_load(sb + ATT_STG, kbase + 128, t);
        cp_commit();

        uint32_t QH[4], QL[4];
        float o[3][4];
#pragma unroll
        for (int i = 0; i < 3; i++)
#pragma unroll
            for (int j = 0; j < 4; j++) o[i][j] = 0.f;
        float m0 = -INFINITY, m8 = -INFINITY;

        int sidx = 0;
        for (int c = 0; c < 16; c++) {
            if (c == 15) cp_wait<0>(); else cp_wait<1>();
            __syncthreads();
            if (c == 0) {
                ldsm4(aQ, QH[0], QH[1], QH[2], QH[3]);
                ldsm4(aQ + (ATT_QL - ATT_QH), QL[0], QL[1], QL[2], QL[3]);
            }
            if (c + 2 < 16) {
                int pidx = sidx + 2; if (pidx >= 3) pidx -= 3;
                attn_load(sb + (uint32_t)pidx * ATT_STG, kbase + (c + 2) * 128, t);
                cp_commit();
            }
            uint32_t stg = sb + (uint32_t)sidx * ATT_STG;

            float s[16][4];
#pragma unroll
            for (int u = 0; u < 8; u++) {
                uint32_t bh0, bh1, bh2, bh3, bl0, bl1, bl2, bl3;
                ldsm4(stg + u * 768 + aK, bh0, bh1, bh2, bh3);
                ldsm4(stg + 6144 + u * 768 + aK, bl0, bl1, bl2, bl3);
                mma16816_z(s[2 * u], QH, bh0, bh1);
                mma16816(s[2 * u], QH, bl0, bl1);
                mma16816(s[2 * u], QL, bh0, bh1);
                mma16816_z(s[2 * u + 1], QH, bh2, bh3);
                mma16816(s[2 * u + 1], QH, bl2, bl3);
                mma16816(s[2 * u + 1], QL, bh2, bh3);
            }

            float mx0 = s[0][0], mx8 = s[0][2];
#pragma unroll
            for (int nt = 0; nt < 16; nt++) {
                mx0 = fmaxf(mx0, fmaxf(s[nt][0], s[nt][1]));
                mx8 = fmaxf(mx8, fmaxf(s[nt][2], s[nt][3]));
            }
            mx0 = fmaxf(mx0, __shfl_xor_sync(0xffffffffu, mx0, 1));
            mx0 = fmaxf(mx0, __shfl_xor_sync(0xffffffffu, mx0, 2));
            mx8 = fmaxf(mx8, __shfl_xor_sync(0xffffffffu, mx8, 1));
            mx8 = fmaxf(mx8, __shfl_xor_sync(0xffffffffu, mx8, 2));
            float mn0 = fmaxf(m0, mx0), mn8 = fmaxf(m8, mx8);
            float c0 = ex2f(m0 - mn0), c8 = ex2f(m8 - mn8);
            m0 = mn0; m8 = mn8;
#pragma unroll
            for (int i = 0; i < 3; i++) {
                o[i][0] *= c0; o[i][1] *= c0; o[i][2] *= c8; o[i][3] *= c8;
            }
#pragma unroll
            for (int nt = 0; nt < 16; nt++) {
                s[nt][0] = ex2f(s[nt][0] - m0);
                s[nt][1] = ex2f(s[nt][1] - m0);
                s[nt][2] = ex2f(s[nt][2] - m8);
                s[nt][3] = ex2f(s[nt][3] - m8);
            }

#pragma unroll
            for (int j = 0; j < 8; j++) {
                uint32_t a[4];
                a[0] = f16x2_pack(s[2 * j][1],     s[2 * j][0]);
                a[1] = f16x2_pack(s[2 * j][3],     s[2 * j][2]);
                a[2] = f16x2_pack(s[2 * j + 1][1], s[2 * j + 1][0]);
                a[3] = f16x2_pack(s[2 * j + 1][3], s[2 * j + 1][2]);
                uint32_t v0, v1, v2, v3, v4, v5;
                ldsm4t(stg + 12288 + j * 768 + aV4, v0, v1, v2, v3);
                ldsm2t(stg + 12288 + j * 768 + aV2, v4, v5);
                mma16816(o[0], a, v0, v1);
                mma16816(o[1], a, v2, v3);
                mma16816(o[2], a, v4, v5);
            }
            if (++sidx == 3) sidx = 0;
        }

        float l0 = __shfl_sync(0xffffffffu, o[2][0], lane & 28);
        float l8 = __shfl_sync(0xffffffffu, o[2][2], lane & 28);
        int row0 = q0 + w * 16 + (lane >> 2);
        int c4 = (lane & 3) * 2;
        *(float2*)&g_po[ks][row0][c4]         = make_float2(o[0][0], o[0][1]);
        *(float2*)&g_po[ks][row0][8 + c4]     = make_float2(o[1][0], o[1][1]);
        *(float2*)&g_po[ks][row0 + 8][c4]     = make_float2(o[0][2], o[0][3]);
        *(float2*)&g_po[ks][row0 + 8][8 + c4] = make_float2(o[1][2], o[1][3]);
        if ((lane & 3) == 0) {
            *(float2*)&g_pml[ks][row0][0]     = make_float2(m0, l0);
            *(float2*)&g_pml[ks][row0 + 8][0] = make_float2(m8, l8);
        }
    }
}

// ---------------- mho = merge(partials) @ Woeff (fp32 + fp16 hi) -----------
__global__ void __launch_bounds__(256) mho_kernel() {
    __shared__ float hrow[8][16];
    int t = threadIdx.x;
    int r0 = blockIdx.x * 8;
    if (t < 128) {
        int row = r0 + (t >> 4), col = t & 15;
        float mm = -INFINITY;
#pragma unroll
        for (int k = 0; k < 4; k++) mm = fmaxf(mm, g_pml[k][row][0]);
        float l = 0.f, acc = 0.f;
#pragma unroll
        for (int k = 0; k < 4; k++) {
            float2 s = *(const float2*)&g_pml[k][row][0];
            float a = ex2f(s.x - mm);
            l = fmaf(s.y, a, l);
            acc = fmaf(g_po[k][row][col], a, acc);
        }
        hrow[t >> 4][col] = acc * __fdividef(1.f, l);
    }
    __syncthreads();

    int cg = (t & 127) * 4;
    int rb = (t >> 7) * 4;
    float4 a[4];
#pragma unroll
    for (int r = 0; r < 4; r++) a[r] = make_float4(0.f, 0.f, 0.f, 0.f);
#pragma unroll
    for (int i = 0; i < 16; i++) {
        float4 w = *(const float4*)&g_Woeff[i * 512 + cg];
#pragma unroll
        for (int r = 0; r < 4; r++) {
            float h = hrow[rb + r][i];
            a[r].x = fmaf(h, w.x, a[r].x); a[r].y = fmaf(h, w.y, a[r].y);
            a[r].z = fmaf(h, w.z, a[r].z); a[r].w = fmaf(h, w.w, a[r].w);
        }
    }
#pragma unroll
    for (int r = 0; r < 4; r++) {
        size_t base = (size_t)(r0 + rb + r) * 512 + cg;
        *(float4*)&g_mho[base] = a[r];
        __half2 h01, h23;
        h01.x = __float2half_rn(a[r].x); h01.y = __float2half_rn(a[r].y);
        h23.x = __float2half_rn(a[r].z); h23.y = __float2half_rn(a[r].w);
        *(__half2*)&g_mhoh[base + 0] = h01;
        *(__half2*)&g_mhoh[base + 2] = h23;
    }
}

// ---------------- fused persistent FFN GEMM kernel -------------------------
// Items [0,1024): gemm1 tiles, gelu epilogue -> g_hh.
// Items [1024,1280): gemm2 tiles, gated on g_cnt[mblk]==16.
static constexpr int G_STAGE = 20480;   // A(10240)+B(10240)
static constexpr int G_SMEM  = 67584;   // epilogue 128x132 fp32 dominates
static constexpr int N_ITEMS = 1024 + 256;

__device__ __forceinline__ void g3_load(uint32_t stg, int m0, int n0, int k0, int t,
                                        int ldk,
                                        const __half* __restrict__ Ah,
                                        const __half* __restrict__ Bh) {
#pragma unroll
    for (int i = 0; i < 2; i++) {
        int q = t + i * 256;
        int r = q >> 2, gr = q & 3;
        uint32_t off = (uint32_t)r * 80 + gr * 16;
        size_t gidx = (size_t)r * ldk + k0 + gr * 8;
        cp16(stg + off,         Ah + (size_t)m0 * ldk + gidx);
        cp16(stg + 10240 + off, Bh + (size_t)n0 * ldk + gidx);
    }
}

__global__ void __launch_bounds__(256, 2) gemm_fused(
    const float* __restrict__ fc1_b, const float* __restrict__ fc2_b,
    float* __restrict__ outf)
{
    extern __shared__ __align__(128) char sm[];
    __shared__ int sm_item;
    uint32_t sbase = smem_u32(sm);

    int t = threadIdx.x;
    int wid = t >> 5, lane = t & 31;
    int wm = wid & 3, wn = wid >> 2;

    int a_row = lane & 15;
    int a_kg  = lane >> 4;
    int b_row = ((lane >> 4) << 3) + (lane & 7);
    int b_kg  = (lane >> 3) & 1;

    for (;;) {
        __syncthreads();
        if (t == 0) sm_item = atomicAdd(&g_gq, 1);
        __syncthreads();
        int item = sm_item;
        if (item >= N_ITEMS) return;

        const __half* Ap;
        const __half* Bp;
        const float* bias;
        int m0, n0, ldk, NC, N, epi, mblk;
        if (item < 1024) {
            mblk = item >> 4;
            m0 = mblk << 7; n0 = (item & 15) << 7;
            Ap = g_mhoh; Bp = g_w1h; bias = fc1_b;
            ldk = DM; NC = DM / 32; N = DFF; epi = 0;
        } else {
            int idx = item - 1024;
            mblk = idx >> 2;
            m0 = mblk << 7; n0 = (idx & 3) << 7;
            Ap = g_hh; Bp = g_w2h; bias = fc2_b;
            ldk = DFF; NC = DFF / 32; N = DM; epi = 1;
            if (t == 0) {                       // wait for gemm1 rows
                while (atomicAdd(&g_cnt[mblk], 0) < 16) {}
            }
            __syncthreads();
            __threadfence();
        }

        float acc[2][8][4];
#pragma unroll
        for (int i = 0; i < 2; i++)
#pragma unroll
            for (int j = 0; j < 8; j++)
#pragma unroll
                for (int k = 0; k < 4; k++) acc[i][j][k] = 0.f;

        g3_load(sbase, m0, n0, 0, t, ldk, Ap, Bp);
        cp_commit();
        g3_load(sbase + G_STAGE, m0, n0, 32, t, ldk, Ap, Bp);
        cp_commit();

        int sidx = 0;
        for (int c = 0; c < NC; c++) {
            if (c == NC - 1) cp_wait<0>(); else cp_wait<1>();
            __syncthreads();
            if (c + 2 < NC) {
                int pidx = sidx + 2; if (pidx >= 3) pidx -= 3;
                g3_load(sbase + (uint32_t)pidx * G_STAGE, m0, n0, (c + 2) * 32, t, ldk, Ap, Bp);
                cp_commit();
            }
            uint32_t stg = sbase + (uint32_t)sidx * G_STAGE;
            uint32_t sAh = stg, sBh = stg + 10240;

#pragma unroll
            for (int ks = 0; ks < 2; ks++) {
                uint32_t ah[2][4];
#pragma unroll
                for (int mt = 0; mt < 2; mt++) {
                    uint32_t off = (uint32_t)(wm * 32 + mt * 16 + a_row) * 80
                                 + (uint32_t)(ks * 32 + a_kg * 16);
                    ldsm4(sAh + off, ah[mt][0], ah[mt][1], ah[mt][2], ah[mt][3]);
                }
#pragma unroll
                for (int np = 0; np < 4; np++) {
                    uint32_t boff = (uint32_t)(wn * 64 + np * 16 + b_row) * 80
                                  + (uint32_t)(ks * 32 + b_kg * 16);
                    uint32_t bh0, bh1, bh2, bh3;
                    ldsm4(sBh + boff, bh0, bh1, bh2, bh3);
#pragma unroll
                    for (int mt = 0; mt < 2; mt++) {
                        mma16816(acc[mt][np * 2 + 0], ah[mt], bh0, bh1);
                        mma16816(acc[mt][np * 2 + 1], ah[mt], bh2, bh3);
                    }
                }
            }
            if (++sidx == 3) sidx = 0;
        }

        // epilogue: stage accums to smem, coalesced out
        __syncthreads();
        float* eb = (float*)sm;                 // 128 x 132 fp32
#pragma unroll
        for (int mt = 0; mt < 2; mt++) {
#pragma unroll
            for (int nt = 0; nt < 8; nt++) {
                int row = wm * 32 + mt * 16 + (lane >> 2);
                int col = wn * 64 + nt * 8 + (lane & 3) * 2;
                float* p0 = &eb[row * 132 + col];
                p0[0] = acc[mt][nt][0]; p0[1] = acc[mt][nt][1];
                float* p1 = &eb[(row + 8) * 132 + col];
                p1[0] = acc[mt][nt][2]; p1[1] = acc[mt][nt][3];
            }
        }
        __syncthreads();

        int cp2 = (t & 63) * 2;
        float b0 = bias[n0 + cp2], b1 = bias[n0 + cp2 + 1];
#pragma unroll 4
        for (int i = 0; i < 32; i++) {
            int row = (t >> 6) + i * 4;
            float2 v = *(float2*)&eb[row * 132 + cp2];
            float x0 = v.x + b0, x1 = v.y + b1;
            size_t oidx = (size_t)(m0 + row) * N + n0 + cp2;
            if (epi == 0) {
                x0 = 0.5f * x0 * (1.0f + erff(x0 * 0.70710678118654752f));
                x1 = 0.5f * x1 * (1.0f + erff(x1 * 0.70710678118654752f));
                __half2 hp;
                hp.x = __float2half_rn(x0); hp.y = __float2half_rn(x1);
                *(__half2*)&g_hh[oidx] = hp;
            } else {
                float2 rr = *(const float2*)&g_mho[oidx];
                *(float2*)&outf[oidx] = make_float2(x0 + rr.x, x1 + rr.y);
            }
        }

        if (epi == 0) {
            __threadfence();
            __syncthreads();
            if (t == 0) atomicAdd(&g_cnt[mblk], 1);
        }
    }
}

// ---------------- launch ---------------------------------------------------
extern "C" void kernel_launch(void* const* d_in, const int* in_sizes, int n_in,
                              void* d_out, int out_size) {
    const float* frame = (const float*)d_in[0];
    const float* W_q   = (const float*)d_in[1];
    const float* W_k   = (const float*)d_in[2];
    const float* W_v   = (const float*)d_in[3];
    const float* W_o   = (const float*)d_in[4];
    const float* fc1_w = (const float*)d_in[5];
    const float* fc1_b = (const float*)d_in[6];
    const float* fc2_w = (const float*)d_in[7];
    const float* fc2_b = (const float*)d_in[8];
    float* out = (float*)d_out;

    cudaFuncSetAttribute(gemm_fused,
                         cudaFuncAttributeMaxDynamicSharedMemorySize, G_SMEM);
    cudaFuncSetAttribute(attn_tc,
                         cudaFuncAttributeMaxDynamicSharedMemorySize, ATT_SMEM);

    pack_weights<<<96, 256>>>(W_q, W_k, W_v, W_o);
    conv_weights<<<(DFF * DM + 255) / 256, 256>>>(fc1_w, fc2_w);
    qkv_kernel<<<S_LEN / 64, 256>>>(frame);
    attn_tc<<<148 * 3, 128, ATT_SMEM>>>();
    mho_kernel<<<S_LEN / 8, 256>>>();
    gemm_fused<<<148 * 2, 256, G_SMEM>>>(fc1_b, fc2_b, out);
}

// round 15
// speedup vs baseline: 1.5240x; 1.0258x over previous
#include <cuda_runtime.h>
#include <cuda_fp16.h>
#include <math.h>
#include <stdint.h>

#define S_LEN 8192
#define DM    512
#define DK    16
#define DFF   2048

// ---------------- scratch (static device globals) -------------------------
__device__ __align__(256) float g_Wqkv[DM * 48];
__device__ __align__(256) float g_Woeff[DK * DM];
__device__ __align__(256) float g_mho[S_LEN * DM];    // fp32 (residual)
__device__ __align__(256) __half g_mhoh[S_LEN * DM];  // mho hi (fp16)
__device__ __align__(256) __half g_hh[S_LEN * DFF];   // gelu(h) fp16
__device__ __align__(256) __half g_w1h[DFF * DM];
__device__ __align__(256) __half g_w2h[DM * DFF];
// attention fp16 operands
__device__ __align__(256) __half g_Qh[S_LEN * DK];    // scaled by 0.25*log2e
__device__ __align__(256) __half g_Ql[S_LEN * DK];
__device__ __align__(256) __half g_Kh[S_LEN * DK];
__device__ __align__(256) __half g_Kl[S_LEN * DK];
__device__ __align__(256) __half g_Vph[S_LEN * 24];   // V padded: col16=1, 17-23=0
// split-KV partials (x4)
__device__ __align__(256) float g_po[4][S_LEN][16];   // unnormalized O
__device__ __align__(256) float g_pml[4][S_LEN][2];   // {m (log2), l}
// work queues + completion counters (reset by qkv_kernel each call)
__device__ int g_gq;
__device__ int g_aq;
__device__ int g_cnt[64];    // gemm1 tiles done per m-block (gates gemm2)

#define QSCALE 0.36067376022224085f   // 0.25 * log2(e)

// ---------------- helpers ---------------------------------------------------
__device__ __forceinline__ uint32_t smem_u32(const void* p) {
    uint32_t a;
    asm("{ .reg .u64 t; cvta.to.shared.u64 t, %1; cvt.u32.u64 %0, t; }" : "=r"(a) : "l"(p));
    return a;
}
__device__ __forceinline__ void cp16(uint32_t dst, const void* src) {
    asm volatile("cp.async.cg.shared.global [%0], [%1], 16;" :: "r"(dst), "l"(src) : "memory");
}
__device__ __forceinline__ void cp_commit() {
    asm volatile("cp.async.commit_group;" ::: "memory");
}
template <int P>
__device__ __forceinline__ void cp_wait() {
    asm volatile("cp.async.wait_group %0;" :: "n"(P) : "memory");
}
__device__ __forceinline__ void ldsm4(uint32_t addr, uint32_t& r0, uint32_t& r1,
                                      uint32_t& r2, uint32_t& r3) {
    asm volatile("ldmatrix.sync.aligned.m8n8.x4.shared.b16 {%0,%1,%2,%3}, [%4];"
                 : "=r"(r0), "=r"(r1), "=r"(r2), "=r"(r3) : "r"(addr));
}
__device__ __forceinline__ void ldsm4t(uint32_t addr, uint32_t& r0, uint32_t& r1,
                                       uint32_t& r2, uint32_t& r3) {
    asm volatile("ldmatrix.sync.aligned.m8n8.x4.trans.shared.b16 {%0,%1,%2,%3}, [%4];"
                 : "=r"(r0), "=r"(r1), "=r"(r2), "=r"(r3) : "r"(addr));
}
__device__ __forceinline__ void ldsm2t(uint32_t addr, uint32_t& r0, uint32_t& r1) {
    asm volatile("ldmatrix.sync.aligned.m8n8.x2.trans.shared.b16 {%0,%1}, [%2];"
                 : "=r"(r0), "=r"(r1) : "r"(addr));
}
__device__ __forceinline__ void mma16816(float* c, const uint32_t* a,
                                         uint32_t b0, uint32_t b1) {
    asm volatile(
        "mma.sync.aligned.m16n8k16.row.col.f32.f16.f16.f32 "
        "{%0,%1,%2,%3}, {%4,%5,%6,%7}, {%8,%9}, {%0,%1,%2,%3};"
        : "+f"(c[0]), "+f"(c[1]), "+f"(c[2]), "+f"(c[3])
        : "r"(a[0]), "r"(a[1]), "r"(a[2]), "r"(a[3]), "r"(b0), "r"(b1));
}
__device__ __forceinline__ void mma16816_z(float* c, const uint32_t* a,
                                           uint32_t b0, uint32_t b1) {
    float z = 0.f;
    asm volatile(
        "mma.sync.aligned.m16n8k16.row.col.f32.f16.f16.f32 "
        "{%0,%1,%2,%3}, {%4,%5,%6,%7}, {%8,%9}, {%10,%10,%10,%10};"
        : "=f"(c[0]), "=f"(c[1]), "=f"(c[2]), "=f"(c[3])
        : "r"(a[0]), "r"(a[1]), "r"(a[2]), "r"(a[3]), "r"(b0), "r"(b1), "f"(z));
}
__device__ __forceinline__ float ex2f(float x) {
    float y;
    asm("ex2.approx.ftz.f32 %0, %1;" : "=f"(y) : "f"(x));
    return y;
}
__device__ __forceinline__ uint32_t f16x2_pack(float hi, float lo) {
    uint32_t d;
    asm("cvt.rn.f16x2.f32 %0, %1, %2;" : "=r"(d) : "f"(hi), "f"(lo));
    return d;
}
__device__ __forceinline__ void h_split(float x, __half& hi, __half& lo) {
    hi = __float2half_rn(x);
    lo = __float2half_rn(x - __half2float(hi));
}

// ---------------- weight packing ------------------------------------------
__global__ void pack_weights(const float* __restrict__ Wq,
                             const float* __restrict__ Wk,
                             const float* __restrict__ Wv,
                             const float* __restrict__ Wo) {
    int idx = blockIdx.x * blockDim.x + threadIdx.x;
    if (idx < DM * 48) {
        int d = idx / 48, c = idx % 48;
        float v;
        if (c < 16)      v = Wq[d * 16 + c];
        else if (c < 32) v = Wk[d * 16 + c - 16];
        else             v = Wv[d * 16 + c - 32];
        g_Wqkv[idx] = v;
    }
    if (idx < DK * DM) {
        int i = idx / DM, c = idx % DM;
        float s = 0.f;
#pragma unroll
        for (int h = 0; h < 8; h++) s += Wo[(h * 16 + i) * DM + c];
        g_Woeff[idx] = s;
    }
}

__global__ void conv_weights(const float* __restrict__ w1, const float* __restrict__ w2) {
    int i = blockIdx.x * blockDim.x + threadIdx.x;
    if (i < DFF * DM) {
        g_w1h[i] = __float2half_rn(w1[i]);
        g_w2h[i] = __float2half_rn(w2[i]);
    }
}

// ---------------- fused QKV projection: 64 rows/CTA, 128 CTAs --------------
__global__ void __launch_bounds__(256) qkv_kernel(const float* __restrict__ frame) {
    __shared__ float Fs[64][33];
    __shared__ float Ws[32][48];
    int t = threadIdx.x;
    int m0 = blockIdx.x * 64;
    int r = t & 63;
    int seg = t >> 6;        // 0..3 -> 12 cols each

    if (blockIdx.x == 0) {   // reset work queues + counters for this call
        if (t == 0) { g_gq = 0; g_aq = 0; }
        if (t < 64) g_cnt[t] = 0;
    }

    float acc[12];
#pragma unroll
    for (int c = 0; c < 12; c++) acc[c] = 0.f;

    int lrow = t >> 2;          // 0..63
    int lds  = (t & 3) * 8;     // 0,8,16,24

    for (int d0 = 0; d0 < DM; d0 += 32) {
        {
            float4 v0 = *(const float4*)&frame[(size_t)(m0 + lrow) * DM + d0 + lds];
            float4 v1 = *(const float4*)&frame[(size_t)(m0 + lrow) * DM + d0 + lds + 4];
            Fs[lrow][lds + 0] = v0.x; Fs[lrow][lds + 1] = v0.y;
            Fs[lrow][lds + 2] = v0.z; Fs[lrow][lds + 3] = v0.w;
            Fs[lrow][lds + 4] = v1.x; Fs[lrow][lds + 5] = v1.y;
            Fs[lrow][lds + 6] = v1.z; Fs[lrow][lds + 7] = v1.w;
        }
        for (int q = t; q < 32 * 48; q += 256)
            Ws[q / 48][q % 48] = g_Wqkv[(d0 + q / 48) * 48 + (q % 48)];
        __syncthreads();
#pragma unroll
        for (int d = 0; d < 32; d++) {
            float f = Fs[r][d];
#pragma unroll
            for (int c = 0; c < 12; c++)
                acc[c] = fmaf(f, Ws[d][seg * 12 + c], acc[c]);
        }
        __syncthreads();
    }
    int row = m0 + r;
#pragma unroll
    for (int c = 0; c < 12; c++) {
        int cg = seg * 12 + c;
        __half h, l;
        if (cg < 16) {
            h_split(acc[c] * QSCALE, h, l);
            g_Qh[row * 16 + cg] = h;
            g_Ql[row * 16 + cg] = l;
        } else if (cg < 32) {
            h_split(acc[c], h, l);
            g_Kh[row * 16 + cg - 16] = h;
            g_Kl[row * 16 + cg - 16] = l;
        } else {
            g_Vph[row * 24 + cg - 32] = __float2half_rn(acc[c]);
        }
    }
    if (seg == 0) {
#pragma unroll
        for (int c2 = 16; c2 < 24; c2++)
            g_Vph[row * 24 + c2] = (c2 == 16) ? __float2half_rn(1.0f) : __float2half_rn(0.0f);
    }
}

// ---------------- persistent tensor-core flash attention --------------------
// 512 items = 128 q-tiles x 4 KV splits, dynamic queue over 444 CTAs.
static constexpr uint32_t ATT_STG  = 18432;   // Kh(6144)+Kl(6144)+Vh(6144)
static constexpr uint32_t ATT_QH   = 55296;   // after 3 stages
static constexpr uint32_t ATT_QL   = 58368;
static constexpr uint32_t ATT_SMEM = 61440;

__device__ __forceinline__ void attn_load(uint32_t stg, int k0, int t) {
#pragma unroll
    for (int i = 0; i < 2; i++) {
        int q = t + i * 128;
        int row = q >> 1, g = q & 1;
        cp16(stg + (uint32_t)row * 48 + g * 16, g_Kh + (size_t)(k0 + row) * 16 + g * 8);
        cp16(stg + 6144 + (uint32_t)row * 48 + g * 16, g_Kl + (size_t)(k0 + row) * 16 + g * 8);
    }
#pragma unroll
    for (int i = 0; i < 3; i++) {
        int q = t + i * 128;
        int row = q / 3, g = q % 3;
        cp16(stg + 12288 + (uint32_t)row * 48 + g * 16, g_Vph + (size_t)(k0 + row) * 24 + g * 8);
    }
}

__global__ void __launch_bounds__(128, 3) attn_tc() {
    extern __shared__ __align__(128) char sm[];
    __shared__ int sm_it;
    uint32_t sb = smem_u32(sm);
    int t = threadIdx.x, lane = t & 31, w = t >> 5;

    uint32_t aQ  = sb + ATT_QH + (uint32_t)(w * 16 + (lane & 15)) * 48 + (uint32_t)(lane >> 4) * 16;
    uint32_t aK  = (uint32_t)((lane & 7) + ((lane >> 4) & 1) * 8) * 48 + (uint32_t)((lane >> 3) & 1) * 16;
    uint32_t aV4 = (uint32_t)((lane & 7) + ((lane >> 3) & 1) * 8) * 48 + (uint32_t)(lane >> 4) * 16;
    uint32_t aV2 = (uint32_t)((lane & 7) + ((lane >> 3) & 1) * 8) * 48 + 32;

    for (;;) {
        __syncthreads();
        if (t == 0) sm_it = atomicAdd(&g_aq, 1);
        __syncthreads();
        int it = sm_it;
        if (it >= 512) return;
        int q0 = (it >> 2) * 64;
        int ks = it & 3;
        int kbase = ks * 2048;

        {
            int row = t >> 1, g = t & 1;
            cp16(sb + ATT_QH + (uint32_t)row * 48 + g * 16, g_Qh + (size_t)(q0 + row) * 16 + g * 8);
            cp16(sb + ATT_QL + (uint32_t)row * 48 + g * 16, g_Ql + (size_t)(q0 + row) * 16 + g * 8);
        }
        attn_load(sb, kbase, t);
        cp_commit();
        attn_load(sb + ATT_STG, kbase + 128, t);
        cp_commit();

        uint32_t QH[4], QL[4];
        float o[3][4];
#pragma unroll
        for (int i = 0; i < 3; i++)
#pragma unroll
            for (int j = 0; j < 4; j++) o[i][j] = 0.f;
        float m0 = -INFINITY, m8 = -INFINITY;

        int sidx = 0;
        for (int c = 0; c < 16; c++) {
            if (c == 15) cp_wait<0>(); else cp_wait<1>();
            __syncthreads();
            if (c == 0) {
                ldsm4(aQ, QH[0], QH[1], QH[2], QH[3]);
                ldsm4(aQ + (ATT_QL - ATT_QH), QL[0], QL[1], QL[2], QL[3]);
            }
            if (c + 2 < 16) {
                int pidx = sidx + 2; if (pidx >= 3) pidx -= 3;
                attn_load(sb + (uint32_t)pidx * ATT_STG, kbase + (c + 2) * 128, t);
                cp_commit();
            }
            uint32_t stg = sb + (uint32_t)sidx * ATT_STG;

            float s[16][4];
#pragma unroll
            for (int u = 0; u < 8; u++) {
                uint32_t bh0, bh1, bh2, bh3, bl0, bl1, bl2, bl3;
                ldsm4(stg + u * 768 + aK, bh0, bh1, bh2, bh3);
                ldsm4(stg + 6144 + u * 768 + aK, bl0, bl1, bl2, bl3);
                mma16816_z(s[2 * u], QH, bh0, bh1);
                mma16816(s[2 * u], QH, bl0, bl1);
                mma16816(s[2 * u], QL, bh0, bh1);
                mma16816_z(s[2 * u + 1], QH, bh2, bh3);
                mma16816(s[2 * u + 1], QH, bl2, bl3);
                mma16816(s[2 * u + 1], QL, bh2, bh3);
            }

            float mx0 = s[0][0], mx8 = s[0][2];
#pragma unroll
            for (int nt = 0; nt < 16; nt++) {
                mx0 = fmaxf(mx0, fmaxf(s[nt][0], s[nt][1]));
                mx8 = fmaxf(mx8, fmaxf(s[nt][2], s[nt][3]));
            }
            mx0 = fmaxf(mx0, __shfl_xor_sync(0xffffffffu, mx0, 1));
            mx0 = fmaxf(mx0, __shfl_xor_sync(0xffffffffu, mx0, 2));
            mx8 = fmaxf(mx8, __shfl_xor_sync(0xffffffffu, mx8, 1));
            mx8 = fmaxf(mx8, __shfl_xor_sync(0xffffffffu, mx8, 2));
            float mn0 = fmaxf(m0, mx0), mn8 = fmaxf(m8, mx8);
            float c0 = ex2f(m0 - mn0), c8 = ex2f(m8 - mn8);
            m0 = mn0; m8 = mn8;
#pragma unroll
            for (int i = 0; i < 3; i++) {
                o[i][0] *= c0; o[i][1] *= c0; o[i][2] *= c8; o[i][3] *= c8;
            }
#pragma unroll
            for (int nt = 0; nt < 16; nt++) {
                s[nt][0] = ex2f(s[nt][0] - m0);
                s[nt][1] = ex2f(s[nt][1] - m0);
                s[nt][2] = ex2f(s[nt][2] - m8);
                s[nt][3] = ex2f(s[nt][3] - m8);
            }

#pragma unroll
            for (int j = 0; j < 8; j++) {
                uint32_t a[4];
                a[0] = f16x2_pack(s[2 * j][1],     s[2 * j][0]);
                a[1] = f16x2_pack(s[2 * j][3],     s[2 * j][2]);
                a[2] = f16x2_pack(s[2 * j + 1][1], s[2 * j + 1][0]);
                a[3] = f16x2_pack(s[2 * j + 1][3], s[2 * j + 1][2]);
                uint32_t v0, v1, v2, v3, v4, v5;
                ldsm4t(stg + 12288 + j * 768 + aV4, v0, v1, v2, v3);
                ldsm2t(stg + 12288 + j * 768 + aV2, v4, v5);
                mma16816(o[0], a, v0, v1);
                mma16816(o[1], a, v2, v3);
                mma16816(o[2], a, v4, v5);
            }
            if (++sidx == 3) sidx = 0;
        }

        float l0 = __shfl_sync(0xffffffffu, o[2][0], lane & 28);
        float l8 = __shfl_sync(0xffffffffu, o[2][2], lane & 28);
        int row0 = q0 + w * 16 + (lane >> 2);
        int c4 = (lane & 3) * 2;
        *(float2*)&g_po[ks][row0][c4]         = make_float2(o[0][0], o[0][1]);
        *(float2*)&g_po[ks][row0][8 + c4]     = make_float2(o[1][0], o[1][1]);
        *(float2*)&g_po[ks][row0 + 8][c4]     = make_float2(o[0][2], o[0][3]);
        *(float2*)&g_po[ks][row0 + 8][8 + c4] = make_float2(o[1][2], o[1][3]);
        if ((lane & 3) == 0) {
            *(float2*)&g_pml[ks][row0][0]     = make_float2(m0, l0);
            *(float2*)&g_pml[ks][row0 + 8][0] = make_float2(m8, l8);
        }
    }
}

// ---------------- mho = merge(partials) @ Woeff (fp32 + fp16 hi) -----------
__global__ void __launch_bounds__(256) mho_kernel() {
    __shared__ float hrow[8][16];
    int t = threadIdx.x;
    int r0 = blockIdx.x * 8;
    if (t < 128) {
        int row = r0 + (t >> 4), col = t & 15;
        float mm = -INFINITY;
#pragma unroll
        for (int k = 0; k < 4; k++) mm = fmaxf(mm, g_pml[k][row][0]);
        float l = 0.f, acc = 0.f;
#pragma unroll
        for (int k = 0; k < 4; k++) {
            float2 s = *(const float2*)&g_pml[k][row][0];
            float a = ex2f(s.x - mm);
            l = fmaf(s.y, a, l);
            acc = fmaf(g_po[k][row][col], a, acc);
        }
        hrow[t >> 4][col] = acc * __fdividef(1.f, l);
    }
    __syncthreads();

    int cg = (t & 127) * 4;
    int rb = (t >> 7) * 4;
    float4 a[4];
#pragma unroll
    for (int r = 0; r < 4; r++) a[r] = make_float4(0.f, 0.f, 0.f, 0.f);
#pragma unroll
    for (int i = 0; i < 16; i++) {
        float4 w = *(const float4*)&g_Woeff[i * 512 + cg];
#pragma unroll
        for (int r = 0; r < 4; r++) {
            float h = hrow[rb + r][i];
            a[r].x = fmaf(h, w.x, a[r].x); a[r].y = fmaf(h, w.y, a[r].y);
            a[r].z = fmaf(h, w.z, a[r].z); a[r].w = fmaf(h, w.w, a[r].w);
        }
    }
#pragma unroll
    for (int r = 0; r < 4; r++) {
        size_t base = (size_t)(r0 + rb + r) * 512 + cg;
        *(float4*)&g_mho[base] = a[r];
        __half2 h01, h23;
        h01.x = __float2half_rn(a[r].x); h01.y = __float2half_rn(a[r].y);
        h23.x = __float2half_rn(a[r].z); h23.y = __float2half_rn(a[r].w);
        *(__half2*)&g_mhoh[base + 0] = h01;
        *(__half2*)&g_mhoh[base + 2] = h23;
    }
}

// ---------------- fused persistent FFN GEMM kernel (KC=64) -----------------
// Items [0,1024): gemm1 tiles, gelu epilogue -> g_hh.
// Items [1024,1280): gemm2 tiles, gated on g_cnt[mblk]==16.
// 3-buffer pipeline; 128x144B rows (conflict-free ldsm stride).
static constexpr int G_TILE  = 18432;   // 128 rows x 144 B
static constexpr int G_STAGE = 36864;   // A + B
static constexpr int G_SMEM  = 110592;  // 3 stages (epilogue 67584 fits inside)
static constexpr int N_ITEMS = 1024 + 256;

__device__ __forceinline__ void g3_load(uint32_t stg, int m0, int n0, int k0, int t,
                                        int ldk,
                                        const __half* __restrict__ Ah,
                                        const __half* __restrict__ Bh) {
#pragma unroll
    for (int i = 0; i < 4; i++) {
        int q = t + i * 256;            // 0..1023: 128 rows x 8 granules(16B)
        int r = q >> 3, gr = q & 7;
        uint32_t off = (uint32_t)r * 144 + gr * 16;
        size_t gidx = (size_t)r * ldk + k0 + gr * 8;
        cp16(stg + off,          Ah + (size_t)m0 * ldk + gidx);
        cp16(stg + G_TILE + off, Bh + (size_t)n0 * ldk + gidx);
    }
}

__global__ void __launch_bounds__(256, 2) gemm_fused(
    const float* __restrict__ fc1_b, const float* __restrict__ fc2_b,
    float* __restrict__ outf)
{
    extern __shared__ __align__(128) char sm[];
    __shared__ int sm_item;
    uint32_t sbase = smem_u32(sm);

    int t = threadIdx.x;
    int wid = t >> 5, lane = t & 31;
    int wm = wid & 3, wn = wid >> 2;

    int a_row = lane & 15;
    int a_kg  = lane >> 4;
    int b_row = ((lane >> 4) << 3) + (lane & 7);
    int b_kg  = (lane >> 3) & 1;

    for (;;) {
        __syncthreads();
        if (t == 0) sm_item = atomicAdd(&g_gq, 1);
        __syncthreads();
        int item = sm_item;
        if (item >= N_ITEMS) return;

        const __half* Ap;
        const __half* Bp;
        const float* bias;
        int m0, n0, ldk, NC, N, epi, mblk;
        if (item < 1024) {
            mblk = item >> 4;
            m0 = mblk << 7; n0 = (item & 15) << 7;
            Ap = g_mhoh; Bp = g_w1h; bias = fc1_b;
            ldk = DM; NC = DM / 64; N = DFF; epi = 0;
        } else {
            int idx = item - 1024;
            mblk = idx >> 2;
            m0 = mblk << 7; n0 = (idx & 3) << 7;
            Ap = g_hh; Bp = g_w2h; bias = fc2_b;
            ldk = DFF; NC = DFF / 64; N = DM; epi = 1;
            if (t == 0) {                       // wait for gemm1 rows
                while (atomicAdd(&g_cnt[mblk], 0) < 16) {}
            }
            __syncthreads();
            __threadfence();
        }

        float acc[2][8][4];
#pragma unroll
        for (int i = 0; i < 2; i++)
#pragma unroll
            for (int j = 0; j < 8; j++)
#pragma unroll
                for (int k = 0; k < 4; k++) acc[i][j][k] = 0.f;

        g3_load(sbase, m0, n0, 0, t, ldk, Ap, Bp);
        cp_commit();
        g3_load(sbase + G_STAGE, m0, n0, 64, t, ldk, Ap, Bp);
        cp_commit();

        int sidx = 0;
        for (int c = 0; c < NC; c++) {
            if (c == NC - 1) cp_wait<0>(); else cp_wait<1>();
            __syncthreads();
            if (c + 2 < NC) {
                int pidx = sidx + 2; if (pidx >= 3) pidx -= 3;
                g3_load(sbase + (uint32_t)pidx * G_STAGE, m0, n0, (c + 2) * 64, t, ldk, Ap, Bp);
                cp_commit();
            }
            uint32_t stg = sbase + (uint32_t)sidx * G_STAGE;
            uint32_t sAh = stg, sBh = stg + G_TILE;

#pragma unroll
            for (int ks = 0; ks < 4; ks++) {
                uint32_t ah[2][4];
#pragma unroll
                for (int mt = 0; mt < 2; mt++) {
                    uint32_t off = (uint32_t)(wm * 32 + mt * 16 + a_row) * 144
                                 + (uint32_t)(ks * 32 + a_kg * 16);
                    ldsm4(sAh + off, ah[mt][0], ah[mt][1], ah[mt][2], ah[mt][3]);
                }
#pragma unroll
                for (int np = 0; np < 4; np++) {
                    uint32_t boff = (uint32_t)(wn * 64 + np * 16 + b_row) * 144
                                  + (uint32_t)(ks * 32 + b_kg * 16);
                    uint32_t bh0, bh1, bh2, bh3;
                    ldsm4(sBh + boff, bh0, bh1, bh2, bh3);
#pragma unroll
                    for (int mt = 0; mt < 2; mt++) {
                        mma16816(acc[mt][np * 2 + 0], ah[mt], bh0, bh1);
                        mma16816(acc[mt][np * 2 + 1], ah[mt], bh2, bh3);
                    }
                }
            }
            if (++sidx == 3) sidx = 0;
        }

        // epilogue: stage accums to smem, coalesced out
        __syncthreads();
        float* eb = (float*)sm;                 // 128 x 132 fp32
#pragma unroll
        for (int mt = 0; mt < 2; mt++) {
#pragma unroll
            for (int nt = 0; nt < 8; nt++) {
                int row = wm * 32 + mt * 16 + (lane >> 2);
                int col = wn * 64 + nt * 8 + (lane & 3) * 2;
                float* p0 = &eb[row * 132 + col];
                p0[0] = acc[mt][nt][0]; p0[1] = acc[mt][nt][1];
                float* p1 = &eb[(row + 8) * 132 + col];
                p1[0] = acc[mt][nt][2]; p1[1] = acc[mt][nt][3];
            }
        }
        __syncthreads();

        int cp2 = (t & 63) * 2;
        float b0 = bias[n0 + cp2], b1 = bias[n0 + cp2 + 1];
#pragma unroll 4
        for (int i = 0; i < 32; i++) {
            int row = (t >> 6) + i * 4;
            float2 v = *(float2*)&eb[row * 132 + cp2];
            float x0 = v.x + b0, x1 = v.y + b1;
            size_t oidx = (size_t)(m0 + row) * N + n0 + cp2;
            if (epi == 0) {
                x0 = 0.5f * x0 * (1.0f + erff(x0 * 0.70710678118654752f));
                x1 = 0.5f * x1 * (1.0f + erff(x1 * 0.70710678118654752f));
                __half2 hp;
                hp.x = __float2half_rn(x0); hp.y = __float2half_rn(x1);
                *(__half2*)&g_hh[oidx] = hp;
            } else {
                float2 rr = *(const float2*)&g_mho[oidx];
                *(float2*)&outf[oidx] = make_float2(x0 + rr.x, x1 + rr.y);
            }
        }

        if (epi == 0) {
            __threadfence();
            __syncthreads();
            if (t == 0) atomicAdd(&g_cnt[mblk], 1);
        }
    }
}

// ---------------- launch ---------------------------------------------------
extern "C" void kernel_launch(void* const* d_in, const int* in_sizes, int n_in,
                              void* d_out, int out_size) {
    const float* frame = (const float*)d_in[0];
    const float* W_q   = (const float*)d_in[1];
    const float* W_k   = (const float*)d_in[2];
    const float* W_v   = (const float*)d_in[3];
    const float* W_o   = (const float*)d_in[4];
    const float* fc1_w = (const float*)d_in[5];
    const float* fc1_b = (const float*)d_in[6];
    const float* fc2_w = (const float*)d_in[7];
    const float* fc2_b = (const float*)d_in[8];
    float* out = (float*)d_out;

    cudaFuncSetAttribute(gemm_fused,
                         cudaFuncAttributeMaxDynamicSharedMemorySize, G_SMEM);
    cudaFuncSetAttribute(attn_tc,
                         cudaFuncAttributeMaxDynamicSharedMemorySize, ATT_SMEM);

    pack_weights<<<96, 256>>>(W_q, W_k, W_v, W_o);
    conv_weights<<<(DFF * DM + 255) / 256, 256>>>(fc1_w, fc2_w);
    qkv_kernel<<<S_LEN / 64, 256>>>(frame);
    attn_tc<<<148 * 3, 128, ATT_SMEM>>>();
    mho_kernel<<<S_LEN / 8, 256>>>();
    gemm_fused<<<148 * 2, 256, G_SMEM>>>(fc1_b, fc2_b, out);
}